// round 1
// baseline (speedup 1.0000x reference)
#include <cuda_runtime.h>
#include <math.h>

#define NNODE 40000
#define EEDGE 640000
#define DD    128
#define HHID  256
#define LNEPS 1e-5f

// ---- scratch (device globals: allocation-free) ----
__device__ float g_A[(size_t)NNODE * HHID];     // sender_x @ ew1[0:128]
__device__ float g_B[(size_t)NNODE * HHID];     // receiver_x @ ew1[128:256] + eb1
__device__ float g_agg[(size_t)NNODE * DD];     // scatter-sum of edge messages
__device__ int   g_cnt[NNODE];                  // per-node edge count
__device__ int   g_is64;                        // edge_index dtype flag

// ---------------- dtype detect for edge_index (int64 vs int32) ----------------
__global__ void k_detect(const void* __restrict__ ei) {
    const long long* p = (const long long*)ei;
    int ok = 1;
    #pragma unroll
    for (int i = 0; i < 32; i++) {
        long long v = p[i];
        if (v < 0 || v >= NNODE) ok = 0;
    }
    g_is64 = ok;
}

__device__ __forceinline__ int eidx(const void* ei, long long pos) {
    return g_is64 ? (int)((const long long*)ei)[pos] : ((const int*)ei)[pos];
}

// ---------------- zero scratch ----------------
__global__ void k_zero() {
    int i = blockIdx.x * 256 + threadIdx.x;   // grid covers NNODE*DD exactly
    g_agg[i] = 0.0f;
    if (i < NNODE) g_cnt[i] = 0;
}

// ---------------- per-node edge counts ----------------
__global__ void k_count(const void* __restrict__ ei) {
    int e = blockIdx.x * 256 + threadIdx.x;   // grid covers EEDGE exactly
    int d = eidx(ei, (long long)EEDGE + e);
    atomicAdd(&g_cnt[d], 1);
}

__device__ __forceinline__ float siluf(float x) {
    return x * (1.0f / (1.0f + expf(-x)));
}

#define FMA44(A_, xv, wv)                                                              \
    A_[0][0] += xv.x * wv.x; A_[0][1] += xv.x * wv.y; A_[0][2] += xv.x * wv.z; A_[0][3] += xv.x * wv.w; \
    A_[1][0] += xv.y * wv.x; A_[1][1] += xv.y * wv.y; A_[1][2] += xv.y * wv.z; A_[1][3] += xv.y * wv.w; \
    A_[2][0] += xv.z * wv.x; A_[2][1] += xv.z * wv.y; A_[2][2] += xv.z * wv.z; A_[2][3] += xv.z * wv.w; \
    A_[3][0] += xv.w * wv.x; A_[3][1] += xv.w * wv.y; A_[3][2] += xv.w * wv.z; A_[3][3] += xv.w * wv.w;

#define FMAROW(yy, hx)                                                  \
    yy[0] += hx * w0.x; yy[1] += hx * w0.y; yy[2] += hx * w0.z; yy[3] += hx * w0.w; \
    yy[4] += hx * w1v.x; yy[5] += hx * w1v.y; yy[6] += hx * w1v.z; yy[7] += hx * w1v.w;

// ---------------- A/B precompute: O[n][h] = sum_k X[n][k] * W[k][h] (+bias) ----------------
// grid (NNODE/64, 4), 256 threads, K=128, 64-col hidden chunk per blockIdx.y
__global__ __launch_bounds__(256) void k_pregemm(
    const float* __restrict__ X, const float* __restrict__ W,
    const float* __restrict__ bias, float* __restrict__ O)
{
    extern __shared__ float sm[];
    float* Xs = sm;              // [128][68] transposed (k-major)
    float* Ws = sm + 128 * 68;   // [128][68]
    int tid = threadIdx.x;
    int row0 = blockIdx.x * 64;
    int h0 = blockIdx.y * 64;

    for (int idx = tid; idx < 64 * 32; idx += 256) {
        int r = idx >> 5, k4 = idx & 31;
        float4 v = *(const float4*)&X[(size_t)(row0 + r) * 128 + k4 * 4];
        Xs[(k4 * 4 + 0) * 68 + r] = v.x;
        Xs[(k4 * 4 + 1) * 68 + r] = v.y;
        Xs[(k4 * 4 + 2) * 68 + r] = v.z;
        Xs[(k4 * 4 + 3) * 68 + r] = v.w;
    }
    for (int idx = tid; idx < 128 * 16; idx += 256) {
        int k = idx >> 4, c4 = idx & 15;
        *(float4*)&Ws[k * 68 + c4 * 4] = *(const float4*)&W[(size_t)k * HHID + h0 + c4 * 4];
    }
    __syncthreads();

    int tx = tid & 15, ty = tid >> 4;
    float acc[4][4] = {};
    #pragma unroll 4
    for (int k = 0; k < 128; k++) {
        float4 xv = *(const float4*)&Xs[k * 68 + ty * 4];
        float4 wv = *(const float4*)&Ws[k * 68 + tx * 4];
        FMA44(acc, xv, wv)
    }
    #pragma unroll
    for (int i = 0; i < 4; i++) {
        float4 o = make_float4(acc[i][0], acc[i][1], acc[i][2], acc[i][3]);
        if (bias) {
            o.x += bias[h0 + tx * 4 + 0];
            o.y += bias[h0 + tx * 4 + 1];
            o.z += bias[h0 + tx * 4 + 2];
            o.w += bias[h0 + tx * 4 + 3];
        }
        *(float4*)&O[(size_t)(row0 + ty * 4 + i) * HHID + h0 + tx * 4] = o;
    }
}

// ---------------- fused MLP+LN(+residual, +scatter for edges) ----------------
// MODE 0: edge (K=128, X=edge_attr, adds gathered A[src]+B[dst] in hidden space,
//          epilogue: edge_out = edge_attr + p, atomicAdd p into g_agg[dst])
// MODE 1: node (K=256, X = [receiver_x | agg/cnt], residual receiver_x)
// MODE 2: sender (K=128, X=sender_x, residual sender_x)
template <int MODE>
__global__ __launch_bounds__(256) void k_fused(
    const float* __restrict__ Xin, const void* __restrict__ ei,
    const float* __restrict__ w1, const float* __restrict__ b1,
    const float* __restrict__ w2, const float* __restrict__ b2,
    const float* __restrict__ gam, const float* __restrict__ bet,
    float* __restrict__ out)
{
    constexpr int K = (MODE == 1) ? 256 : 128;
    extern __shared__ float sm[];
    float* Xs = sm;                                 // [K][68] transposed
    float* Ws = Xs + K * 68;                        // union: W1 chunk [K][68] / W2 chunk [64][132]
    float* Hs = Ws + ((K * 68 > 64 * 132) ? K * 68 : 64 * 132);  // [64][68] transposed hidden chunk
    int*   sidx = (int*)(Hs + 64 * 68);
    int*   didx = sidx + 64;
    float* rc = (float*)sidx;

    int tid = threadIdx.x;
    int row0 = blockIdx.x * 64;

    // ---- assemble Xs (k-major / transposed) ----
    if (MODE == 0) {
        if (tid < 64) {
            sidx[tid] = eidx(ei, (long long)(row0 + tid));
            didx[tid] = eidx(ei, (long long)EEDGE + row0 + tid);
        }
        for (int idx = tid; idx < 64 * 32; idx += 256) {
            int r = idx >> 5, k4 = idx & 31;
            float4 v = *(const float4*)&Xin[(size_t)(row0 + r) * 128 + k4 * 4];
            Xs[(k4 * 4 + 0) * 68 + r] = v.x;
            Xs[(k4 * 4 + 1) * 68 + r] = v.y;
            Xs[(k4 * 4 + 2) * 68 + r] = v.z;
            Xs[(k4 * 4 + 3) * 68 + r] = v.w;
        }
    } else if (MODE == 2) {
        for (int idx = tid; idx < 64 * 32; idx += 256) {
            int r = idx >> 5, k4 = idx & 31;
            float4 v = *(const float4*)&Xin[(size_t)(row0 + r) * 128 + k4 * 4];
            Xs[(k4 * 4 + 0) * 68 + r] = v.x;
            Xs[(k4 * 4 + 1) * 68 + r] = v.y;
            Xs[(k4 * 4 + 2) * 68 + r] = v.z;
            Xs[(k4 * 4 + 3) * 68 + r] = v.w;
        }
    } else {
        if (tid < 64) {
            int c = g_cnt[row0 + tid];
            rc[tid] = 1.0f / (float)(c > 1 ? c : 1);
        }
        for (int idx = tid; idx < 64 * 32; idx += 256) {
            int r = idx >> 5, k4 = idx & 31;
            float4 v = *(const float4*)&Xin[(size_t)(row0 + r) * 128 + k4 * 4];
            Xs[(k4 * 4 + 0) * 68 + r] = v.x;
            Xs[(k4 * 4 + 1) * 68 + r] = v.y;
            Xs[(k4 * 4 + 2) * 68 + r] = v.z;
            Xs[(k4 * 4 + 3) * 68 + r] = v.w;
        }
        __syncthreads();   // rc ready
        for (int idx = tid; idx < 64 * 32; idx += 256) {
            int r = idx >> 5, k4 = idx & 31;
            float s = rc[r];
            float4 v = *(const float4*)&g_agg[(size_t)(row0 + r) * 128 + k4 * 4];
            Xs[(128 + k4 * 4 + 0) * 68 + r] = v.x * s;
            Xs[(128 + k4 * 4 + 1) * 68 + r] = v.y * s;
            Xs[(128 + k4 * 4 + 2) * 68 + r] = v.z * s;
            Xs[(128 + k4 * 4 + 3) * 68 + r] = v.w * s;
        }
    }
    __syncthreads();

    int tx = tid & 15, ty = tid >> 4;
    float y[4][8] = {};

    #pragma unroll 1
    for (int hc = 0; hc < 4; hc++) {
        int h0 = hc * 64;
        // stage W1 chunk [K][64]
        for (int idx = tid; idx < K * 16; idx += 256) {
            int k = idx >> 4, c4 = idx & 15;
            *(float4*)&Ws[k * 68 + c4 * 4] = *(const float4*)&w1[(size_t)k * HHID + h0 + c4 * 4];
        }
        __syncthreads();

        float h[4][4] = {};
        #pragma unroll 4
        for (int k = 0; k < K; k++) {
            float4 xv = *(const float4*)&Xs[k * 68 + ty * 4];
            float4 wv = *(const float4*)&Ws[k * 68 + tx * 4];
            FMA44(h, xv, wv)
        }

        if (MODE == 0) {
            #pragma unroll
            for (int i = 0; i < 4; i++) {
                int r = ty * 4 + i;
                float4 av = *(const float4*)&g_A[(size_t)sidx[r] * HHID + h0 + tx * 4];
                float4 bv = *(const float4*)&g_B[(size_t)didx[r] * HHID + h0 + tx * 4];
                h[i][0] += av.x + bv.x;
                h[i][1] += av.y + bv.y;
                h[i][2] += av.z + bv.z;
                h[i][3] += av.w + bv.w;
            }
        } else {
            float4 bv = *(const float4*)&b1[h0 + tx * 4];
            #pragma unroll
            for (int i = 0; i < 4; i++) {
                h[i][0] += bv.x; h[i][1] += bv.y; h[i][2] += bv.z; h[i][3] += bv.w;
            }
        }

        // SiLU + store hidden chunk transposed: Hs[col][row]
        #pragma unroll
        for (int j = 0; j < 4; j++) {
            float4 hv;
            hv.x = siluf(h[0][j]);
            hv.y = siluf(h[1][j]);
            hv.z = siluf(h[2][j]);
            hv.w = siluf(h[3][j]);
            *(float4*)&Hs[(tx * 4 + j) * 68 + ty * 4] = hv;
        }
        __syncthreads();   // Hs ready, W1 reads done

        // stage W2 chunk [64][128]
        for (int idx = tid; idx < 64 * 32; idx += 256) {
            int k = idx >> 5, c4 = idx & 31;
            *(float4*)&Ws[k * 132 + c4 * 4] = *(const float4*)&w2[(size_t)(h0 + k) * 128 + c4 * 4];
        }
        __syncthreads();

        #pragma unroll 2
        for (int k = 0; k < 64; k++) {
            float4 hv = *(const float4*)&Hs[k * 68 + ty * 4];
            float4 w0 = *(const float4*)&Ws[k * 132 + tx * 8];
            float4 w1v = *(const float4*)&Ws[k * 132 + tx * 8 + 4];
            FMAROW(y[0], hv.x)
            FMAROW(y[1], hv.y)
            FMAROW(y[2], hv.z)
            FMAROW(y[3], hv.w)
        }
        __syncthreads();   // W2 reads done before next chunk overwrites Ws
    }

    // ---- epilogue: +b2, LayerNorm, gamma/beta, residual, store (+scatter) ----
    float b2r[8], gr[8], br[8];
    #pragma unroll
    for (int c = 0; c < 8; c++) {
        b2r[c] = b2[tx * 8 + c];
        gr[c] = gam[tx * 8 + c];
        br[c] = bet[tx * 8 + c];
    }
    #pragma unroll
    for (int i = 0; i < 4; i++) {
        #pragma unroll
        for (int c = 0; c < 8; c++) y[i][c] += b2r[c];

        float s1 = 0.f, s2 = 0.f;
        #pragma unroll
        for (int c = 0; c < 8; c++) { float v = y[i][c]; s1 += v; s2 += v * v; }
        #pragma unroll
        for (int m = 8; m >= 1; m >>= 1) {
            s1 += __shfl_xor_sync(0xffffffffu, s1, m);
            s2 += __shfl_xor_sync(0xffffffffu, s2, m);
        }
        float mu = s1 * (1.0f / 128.0f);
        float rs = rsqrtf(s2 * (1.0f / 128.0f) - mu * mu + LNEPS);

        int r = ty * 4 + i;
        float o[8];
        #pragma unroll
        for (int c = 0; c < 8; c++) {
            float p = (y[i][c] - mu) * rs * gr[c] + br[c];
            y[i][c] = p;                              // keep p for scatter
            o[c] = p + Xs[(tx * 8 + c) * 68 + r];     // residual from original input
        }
        size_t gout = (size_t)(row0 + r) * 128 + tx * 8;
        *(float4*)&out[gout]     = make_float4(o[0], o[1], o[2], o[3]);
        *(float4*)&out[gout + 4] = make_float4(o[4], o[5], o[6], o[7]);

        if (MODE == 0) {
            int d = didx[r];
            float* ap = &g_agg[(size_t)d * 128 + tx * 8];
            #pragma unroll
            for (int c = 0; c < 8; c++) atomicAdd(ap + c, y[i][c]);
        }
    }
}

// ---------------- launcher ----------------
extern "C" void kernel_launch(void* const* d_in, const int* in_sizes, int n_in,
                              void* d_out, int out_size) {
    (void)in_sizes; (void)n_in; (void)out_size;
    const float* sender_x   = (const float*)d_in[0];
    const float* receiver_x = (const float*)d_in[1];
    const float* edge_attr  = (const float*)d_in[2];
    const void*  ei         = d_in[3];
    const float* ew1  = (const float*)d_in[4];
    const float* eb1  = (const float*)d_in[5];
    const float* ew2  = (const float*)d_in[6];
    const float* eb2  = (const float*)d_in[7];
    const float* eg   = (const float*)d_in[8];
    const float* ebt  = (const float*)d_in[9];
    const float* nw1  = (const float*)d_in[10];
    const float* nb1  = (const float*)d_in[11];
    const float* nw2  = (const float*)d_in[12];
    const float* nb2  = (const float*)d_in[13];
    const float* ng   = (const float*)d_in[14];
    const float* nbt  = (const float*)d_in[15];
    const float* sw1  = (const float*)d_in[16];
    const float* sb1  = (const float*)d_in[17];
    const float* sw2  = (const float*)d_in[18];
    const float* sb2  = (const float*)d_in[19];
    const float* sg   = (const float*)d_in[20];
    const float* sbt  = (const float*)d_in[21];

    float* out = (float*)d_out;
    float* out_send = out;
    float* out_recv = out + (size_t)NNODE * DD;
    float* out_edge = out + (size_t)2 * NNODE * DD;

    void *pA, *pB;
    cudaGetSymbolAddress(&pA, g_A);
    cudaGetSymbolAddress(&pB, g_B);

    const int SM_PRE = (128 * 68 + 128 * 68) * 4;                       // 69632
    const int SM_EK  = (128 * 68 + 128 * 68 + 64 * 68 + 128) * 4;       // 87552
    const int SM_NK  = (256 * 68 + 256 * 68 + 64 * 68 + 64) * 4;        // 156928
    cudaFuncSetAttribute(k_pregemm,  cudaFuncAttributeMaxDynamicSharedMemorySize, SM_PRE);
    cudaFuncSetAttribute(k_fused<0>, cudaFuncAttributeMaxDynamicSharedMemorySize, SM_EK);
    cudaFuncSetAttribute(k_fused<1>, cudaFuncAttributeMaxDynamicSharedMemorySize, SM_NK);
    cudaFuncSetAttribute(k_fused<2>, cudaFuncAttributeMaxDynamicSharedMemorySize, SM_EK);

    k_detect<<<1, 1>>>(ei);
    k_zero<<<(NNODE * DD) / 256, 256>>>();
    k_count<<<EEDGE / 256, 256>>>(ei);
    // A = sender_x @ ew1[0:128,:]      (no bias)
    k_pregemm<<<dim3(NNODE / 64, 4), 256, SM_PRE>>>(sender_x, ew1, nullptr, (float*)pA);
    // B = receiver_x @ ew1[128:256,:] + eb1
    k_pregemm<<<dim3(NNODE / 64, 4), 256, SM_PRE>>>(receiver_x, ew1 + 128 * HHID, eb1, (float*)pB);
    // edge MLP + LN + residual + scatter
    k_fused<0><<<EEDGE / 64, 256, SM_EK>>>(edge_attr, ei, ew1 + 256 * HHID, eb1,
                                           ew2, eb2, eg, ebt, out_edge);
    // sender MLP (independent)
    k_fused<2><<<NNODE / 64, 256, SM_EK>>>(sender_x, nullptr, sw1, sb1,
                                           sw2, sb2, sg, sbt, out_send);
    // node MLP (consumes g_agg/g_cnt)
    k_fused<1><<<NNODE / 64, 256, SM_NK>>>(receiver_x, nullptr, nw1, nb1,
                                           nw2, nb2, ng, nbt, out_recv);
}